// round 15
// baseline (speedup 1.0000x reference)
#include <cuda_runtime.h>
#include <cstdint>

// Depthwise causal FIR conv1d, K=31, fp32.
// x: (8, 4096, 2048) channel-last.  w: (2048, 31).  y like x.
//
// Round-15: R14 minimum-liveness window + IMMEDIATE-OFFSET addressing + cap.
//  - every steady-state LDG/STG is [Rbase + IMM]: one loop-invariant base
//    pointer per stream, compile-time element offsets (max 1.29 MB < 8 MB imm)
//    -> no address-batch registers -> a reg cap can no longer serialize loads
//    (the actual mechanism behind the R9/R11/R12 cap collapses: L1% fell,
//    so they were address-scheduling collapses, not value spills)
//  - 30-slot circular window, refill folded into tap groups 0..7 (23-tap lead)
//  - taps: pinned smem (asm-volatile LDS.64, 3-slot rotation)
//  - __launch_bounds__(64, 8): 128-reg cap, demand ~95 -> 16 warps/SM

#define BB 8
#define LL 4096
#define CPAIR 1024
#define KK 31
#define CHUNK 8
#define TT 128
#define NCHUNK 16
#define WBUF 30
#define THREADS 64

__device__ __forceinline__ float2 ffma2(float2 a, float2 b, float2 c) {
    float2 d;
    asm("fma.rn.f32x2 %0, %1, %2, %3;"
        : "=l"(*reinterpret_cast<unsigned long long*>(&d))
        : "l"(*reinterpret_cast<const unsigned long long*>(&a)),
          "l"(*reinterpret_cast<const unsigned long long*>(&b)),
          "l"(*reinterpret_cast<const unsigned long long*>(&c)));
    return d;
}

// Pinned LDS.64: volatile keeps ptxas from hoisting/batching weight loads.
__device__ __forceinline__ float2 lds_wt(uint32_t addr) {
    float2 v;
    asm volatile("ld.shared.v2.f32 {%0, %1}, [%2];"
                 : "=f"(v.x), "=f"(v.y) : "r"(addr));
    return v;
}

__global__ __launch_bounds__(THREADS, 8)
void _DepthwiseFIRConv1d_kernel(const float* __restrict__ x,
                                const float* __restrict__ w,
                                float* __restrict__ y) {
    __shared__ float2 ws[KK][THREADS];                   // 15872 B

    const int tid = threadIdx.x;
    const int cpi = blockIdx.x * THREADS + tid;          // channel pair 0..1023
    const int l0  = blockIdx.y * TT;
    const int b   = blockIdx.z;

    const float2* xb = reinterpret_cast<const float2*>(x) + (size_t)b * LL * CPAIR + cpi;
    float2*       ys = reinterpret_cast<float2*>(y) + ((size_t)b * LL + l0) * CPAIR + cpi;
    const int base = l0 - (KK - 1);                      // x offset of window origin
    // Loop-invariant base: steady-state access = xs[CONST * CPAIR] -> LDG [R+IMM].
    const float2* xs = xb + (ptrdiff_t)base * CPAIR;

    // Stage taps into smem: ws[t][tid] = (w[2cp][t], w[2cp+1][t]).
    {
        const float* w0 = w + (2 * cpi) * KK;
#pragma unroll
        for (int t = 0; t < KK; t++)
            ws[t][tid] = make_float2(__ldg(w0 + t), __ldg(w0 + KK + t));
    }
    __syncthreads();

    const uint32_t ws0 = (uint32_t)__cvta_generic_to_shared(&ws[0][tid]);

    // Initial window: offsets 0..29. Uniform branch: only l0==0 blocks predicate.
    float2 buf[WBUF];
    if (l0 != 0) {
#pragma unroll
        for (int i = 0; i < WBUF; i++)
            buf[i] = xs[i * CPAIR];                      // LDG [R+IMM]
    } else {
#pragma unroll
        for (int i = 0; i < WBUF; i++) {
            const int l = base + i;
            buf[i] = (l >= 0) ? xb[(size_t)l * CPAIR] : make_float2(0.0f, 0.0f);
        }
    }

#pragma unroll
    for (int c = 0; c < NCHUNK; c++) {
        float2 acc[CHUNK];
#pragma unroll
        for (int j = 0; j < CHUNK; j++) acc[j] = make_float2(0.0f, 0.0f);

        // 3-slot rotating weight buffer (3-tap lead >= LDS latency).
        float2 wr[3];
        wr[0] = lds_wt(ws0 + 0 * (THREADS * 8));
        wr[1] = lds_wt(ws0 + 1 * (THREADS * 8));
        wr[2] = lds_wt(ws0 + 2 * (THREADS * 8));

#pragma unroll
        for (int t = 0; t < KK; t++) {
            const float2 wt = wr[t % 3];
#pragma unroll
            for (int j = 0; j < CHUNK; j++)
                acc[j] = ffma2(wt, buf[(CHUNK * c + t + j) % WBUF], acc[j]);

            if (t + 3 < KK)
                wr[t % 3] = lds_wt(ws0 + (uint32_t)(t + 3) * (THREADS * 8));

            // Slot (8c+t)%30 took its last read (j=0 above). Refill with offset
            // 8c+30+t (first consumer: tap t+23 of THIS chunk -> runs every
            // chunk). l = l0+8c+t in [l0, l0+127]: always in range -> [R+IMM].
            if (t < CHUNK) {
                const int off = CHUNK * c + WBUF + t;    // compile-time
                buf[(CHUNK * c + t) % WBUF] = xs[off * CPAIR];
            }
        }

#pragma unroll
        for (int j = 0; j < CHUNK; j++)
            ys[(CHUNK * c + j) * CPAIR] = acc[j];        // STG [R+IMM]
    }
}

extern "C" void kernel_launch(void* const* d_in, const int* in_sizes, int n_in,
                              void* d_out, int out_size) {
    const float* x = (const float*)d_in[0];   // (8, 4096, 16, 128)
    const float* w = (const float*)d_in[1];   // (16, 128, 31)
    float* yv = (float*)d_out;

    dim3 grid(CPAIR / THREADS, LL / TT, BB);  // (16, 32, 8) = 4096 blocks
    _DepthwiseFIRConv1d_kernel<<<grid, THREADS>>>(x, w, yv);
}

// round 16
// speedup vs baseline: 1.6515x; 1.6515x over previous
#include <cuda_runtime.h>
#include <cstdint>

// Depthwise causal FIR conv1d, K=31, fp32.
// x: (8, 4096, 2048) channel-last.  w: (2048, 31).  y like x.
//
// Round-16: R5 (best, 105us) with a DEEPER cp.async pipeline.
//  - RINGB 8 (32KB ring): 8 committed groups in flight -> ~4KB/warp in flight,
//    consumption lead = 8 chunks (~4000 cyc) -> DRAM arrival fully hidden
//  - wait_group 7; epilogue: wait -> consume batch c+1 -> issue batch c+9
//    into the just-freed slot ((c+9)&7 == (c+1)&7)
//  - weights in registers (R5 style), 38-slot register window, FFMA2 math
//  - st.global.cs for y (write-once; preserve L2 for x halo)
//  - NO launch_bounds cap (5/5 capped rounds collapsed)

#define BB 8
#define LL 4096
#define CP 1024          // channel pairs
#define KK 31
#define CHUNK 8
#define TT 128
#define NCHUNK 16
#define WBUF 38          // 30 halo + 8 current
#define THREADS 64
#define RINGB 8          // cp.async batches in flight

__device__ __forceinline__ float2 ffma2(float2 a, float2 b, float2 c) {
    float2 d;
    asm("fma.rn.f32x2 %0, %1, %2, %3;"
        : "=l"(*reinterpret_cast<unsigned long long*>(&d))
        : "l"(*reinterpret_cast<const unsigned long long*>(&a)),
          "l"(*reinterpret_cast<const unsigned long long*>(&b)),
          "l"(*reinterpret_cast<const unsigned long long*>(&c)));
    return d;
}

__device__ __forceinline__ void cp_async8(uint32_t saddr, const void* gptr) {
    asm volatile("cp.async.ca.shared.global [%0], [%1], 8;"
                 :: "r"(saddr), "l"(gptr) : "memory");
}
__device__ __forceinline__ void cp_commit() {
    asm volatile("cp.async.commit_group;" ::: "memory");
}
__device__ __forceinline__ void cp_wait7() {
    asm volatile("cp.async.wait_group 7;" ::: "memory");
}

__device__ __forceinline__ void stg_cs(float2* p, float2 v) {
    asm volatile("st.global.cs.v2.f32 [%0], {%1, %2};"
                 :: "l"(p), "f"(v.x), "f"(v.y) : "memory");
}

__global__ __launch_bounds__(THREADS)
void _DepthwiseFIRConv1d_kernel(const float* __restrict__ x,
                                const float* __restrict__ w,
                                float* __restrict__ y) {
    // ring[row][tid]: row = (batch & 7)*8 + i; per-thread column -> conflict-free
    __shared__ float2 ring[RINGB * CHUNK][THREADS];      // 32 KB

    const int tid = threadIdx.x;
    const int cp  = blockIdx.x * THREADS + tid;          // channel pair 0..1023
    const int l0  = blockIdx.y * TT;
    const int b   = blockIdx.z;

    const float2* xb = reinterpret_cast<const float2*>(x) + (size_t)b * LL * CP + cp;
    float2*       yb = reinterpret_cast<float2*>(y) + ((size_t)b * LL + l0) * CP + cp;
    const int base = l0 - (KK - 1);

    const uint32_t s0 = (uint32_t)__cvta_generic_to_shared(&ring[0][tid]);

    // Taps for both channels -> registers (reused for 128 outputs).
    const float* w0 = w + (2 * cp) * KK;
    float2 wt[KK];
#pragma unroll
    for (int t = 0; t < KK; t++)
        wt[t] = make_float2(__ldg(w0 + t), __ldg(w0 + KK + t));

    // Initial window: offsets 0..37 (chunk 0's span). Predicate only for l0==0.
    float2 buf[WBUF];
#pragma unroll
    for (int i = 0; i < WBUF; i++) {
        const int l = base + i;
        buf[i] = (l >= 0) ? xb[(size_t)l * CP] : make_float2(0.0f, 0.0f);
    }

    // Prologue: issue batches 1..8 (batch k = offsets 8k+30 .. 8k+37, consumed
    // at the END of chunk k-1). l = l0 + 8(k-1) + i: in [l0, l0+71], in range.
#pragma unroll
    for (int k = 1; k <= RINGB; k++) {
#pragma unroll
        for (int i = 0; i < CHUNK; i++) {
            const int off = 8 * k + 30 + i;
            cp_async8(s0 + (uint32_t)(((k & 7) * CHUNK + i) * (THREADS * 8)),
                      xb + (size_t)(base + off) * CP);
        }
        cp_commit();
    }

#pragma unroll
    for (int c = 0; c < NCHUNK; c++) {
        float2 acc[CHUNK];
#pragma unroll
        for (int j = 0; j < CHUNK; j++) acc[j] = make_float2(0.0f, 0.0f);

#pragma unroll
        for (int t = 0; t < KK; t++) {
#pragma unroll
            for (int j = 0; j < CHUNK; j++) {
                acc[j] = ffma2(wt[t], buf[(CHUNK * c + j + t) % WBUF], acc[j]);
            }
        }

#pragma unroll
        for (int j = 0; j < CHUNK; j++)
            stg_cs(yb + (size_t)(CHUNK * c + j) * CP, acc[j]);

        if (c < NCHUNK - 1) {
            // 1) wait: with <=8 pending groups, batch c+1 is complete
            cp_wait7();
            // 2) consume batch c+1: offsets 8c+38+i -> slot (8c+i) % 38 (retired)
#pragma unroll
            for (int i = 0; i < CHUNK; i++)
                buf[(CHUNK * c + i) % WBUF] = ring[((c + 1) & 7) * CHUNK + i][tid];
            // 3) issue batch c+9 into the slot just consumed
            if (c + 9 <= NCHUNK - 1) {
#pragma unroll
                for (int i = 0; i < CHUNK; i++) {
                    const int k = c + 9;
                    const int off = 8 * k + 30 + i;
                    cp_async8(s0 + (uint32_t)(((k & 7) * CHUNK + i) * (THREADS * 8)),
                              xb + (size_t)(base + off) * CP);
                }
            }
            cp_commit();   // empty groups in the tail keep the count uniform
        }
    }
}

extern "C" void kernel_launch(void* const* d_in, const int* in_sizes, int n_in,
                              void* d_out, int out_size) {
    const float* x = (const float*)d_in[0];   // (8, 4096, 16, 128)
    const float* w = (const float*)d_in[1];   // (16, 128, 31)
    float* yv = (float*)d_out;

    dim3 grid(CP / THREADS, LL / TT, BB);     // (16, 32, 8) = 4096 blocks
    _DepthwiseFIRConv1d_kernel<<<grid, THREADS>>>(x, w, yv);
}

// round 17
// speedup vs baseline: 1.6585x; 1.0042x over previous
#include <cuda_runtime.h>
#include <cstdint>

// Depthwise causal FIR conv1d, K=31, fp32.
// x: (8, 4096, 2048) channel-last.  w: (2048, 31).  y like x.
//
// Round-17: R5 (best, 105us) with TT=256 to amortize per-tile overhead.
//  - per thread-tile one-time cost (38-slot window fill + 62 weight LDGs)
//    now amortized over 256 outputs instead of 128; halo amp 1.23 -> 1.12
//  - everything else IDENTICAL to R5: 38-slot register window (static mod-38),
//    weights in registers, 4-deep cp.async ring (16KB), wait->consume->issue,
//    FFMA2 math, plain STG, no launch_bounds cap.

#define BB 8
#define LL 4096
#define CP 1024          // channel pairs
#define KK 31
#define CHUNK 8
#define TT 256
#define NCHUNK 32
#define WBUF 38          // 30 halo + 8 current
#define THREADS 64
#define RINGB 4          // cp.async batches in flight

__device__ __forceinline__ float2 ffma2(float2 a, float2 b, float2 c) {
    float2 d;
    asm("fma.rn.f32x2 %0, %1, %2, %3;"
        : "=l"(*reinterpret_cast<unsigned long long*>(&d))
        : "l"(*reinterpret_cast<const unsigned long long*>(&a)),
          "l"(*reinterpret_cast<const unsigned long long*>(&b)),
          "l"(*reinterpret_cast<const unsigned long long*>(&c)));
    return d;
}

__device__ __forceinline__ void cp_async8(uint32_t saddr, const void* gptr) {
    asm volatile("cp.async.ca.shared.global [%0], [%1], 8;"
                 :: "r"(saddr), "l"(gptr) : "memory");
}
__device__ __forceinline__ void cp_commit() {
    asm volatile("cp.async.commit_group;" ::: "memory");
}
__device__ __forceinline__ void cp_wait3() {
    asm volatile("cp.async.wait_group 3;" ::: "memory");
}

__global__ __launch_bounds__(THREADS)
void _DepthwiseFIRConv1d_kernel(const float* __restrict__ x,
                                const float* __restrict__ w,
                                float* __restrict__ y) {
    // ring[row][tid]: row = (batch & 3)*8 + i; per-thread column -> conflict-free
    __shared__ float2 ring[RINGB * CHUNK][THREADS];      // 16 KB

    const int tid = threadIdx.x;
    const int cp  = blockIdx.x * THREADS + tid;          // channel pair 0..1023
    const int l0  = blockIdx.y * TT;
    const int b   = blockIdx.z;

    const float2* xb = reinterpret_cast<const float2*>(x) + (size_t)b * LL * CP + cp;
    float2*       yb = reinterpret_cast<float2*>(y) + ((size_t)b * LL + l0) * CP + cp;
    const int base = l0 - (KK - 1);

    const uint32_t s0 = (uint32_t)__cvta_generic_to_shared(&ring[0][tid]);

    // Taps for both channels -> registers (amortized over 256 outputs now).
    const float* w0 = w + (2 * cp) * KK;
    float2 wt[KK];
#pragma unroll
    for (int t = 0; t < KK; t++)
        wt[t] = make_float2(__ldg(w0 + t), __ldg(w0 + KK + t));

    // Initial window: offsets 0..37 (chunk 0's span). Predicate only for l0==0.
    float2 buf[WBUF];
#pragma unroll
    for (int i = 0; i < WBUF; i++) {
        const int l = base + i;
        buf[i] = (l >= 0) ? xb[(size_t)l * CP] : make_float2(0.0f, 0.0f);
    }

    // Prologue: issue batches 1..4 (batch k = offsets 8k+30 .. 8k+37, consumed
    // at the END of chunk k-1). l = l0 + 8(k-1) + i: in range.
#pragma unroll
    for (int k = 1; k <= RINGB; k++) {
#pragma unroll
        for (int i = 0; i < CHUNK; i++) {
            const int off = 8 * k + 30 + i;
            cp_async8(s0 + (uint32_t)(((k & 3) * CHUNK + i) * (THREADS * 8)),
                      xb + (size_t)(base + off) * CP);
        }
        cp_commit();
    }

#pragma unroll
    for (int c = 0; c < NCHUNK; c++) {
        float2 acc[CHUNK];
#pragma unroll
        for (int j = 0; j < CHUNK; j++) acc[j] = make_float2(0.0f, 0.0f);

#pragma unroll
        for (int t = 0; t < KK; t++) {
#pragma unroll
            for (int j = 0; j < CHUNK; j++) {
                acc[j] = ffma2(wt[t], buf[(CHUNK * c + j + t) % WBUF], acc[j]);
            }
        }

#pragma unroll
        for (int j = 0; j < CHUNK; j++)
            yb[(size_t)(CHUNK * c + j) * CP] = acc[j];

        if (c < NCHUNK - 1) {
            // 1) wait: oldest of the <=4 pending groups (batch c+1) completes
            cp_wait3();
            // 2) consume batch c+1: offsets 8c+38+i -> slot (8c+i) % 38 (retired)
#pragma unroll
            for (int i = 0; i < CHUNK; i++)
                buf[(CHUNK * c + i) % WBUF] = ring[((c + 1) & 3) * CHUNK + i][tid];
            // 3) issue batch c+5 into the slot just consumed ((c+5)&3 == (c+1)&3)
            // l = l0 + 8(c+5) - 8 + i ... = l0 + 8c + 32 + ... always < l0+256.
            if (c + 5 <= NCHUNK - 1) {
#pragma unroll
                for (int i = 0; i < CHUNK; i++) {
                    const int k = c + 5;
                    const int off = 8 * k + 30 + i;
                    cp_async8(s0 + (uint32_t)(((k & 3) * CHUNK + i) * (THREADS * 8)),
                              xb + (size_t)(base + off) * CP);
                }
            }
            cp_commit();   // empty groups in the tail keep the count uniform
        }
    }
}

extern "C" void kernel_launch(void* const* d_in, const int* in_sizes, int n_in,
                              void* d_out, int out_size) {
    const float* x = (const float*)d_in[0];   // (8, 4096, 16, 128)
    const float* w = (const float*)d_in[1];   // (16, 128, 31)
    float* yv = (float*)d_out;

    dim3 grid(CP / THREADS, LL / TT, BB);     // (16, 16, 8) = 2048 blocks
    _DepthwiseFIRConv1d_kernel<<<grid, THREADS>>>(x, w, yv);
}